// round 13
// baseline (speedup 1.0000x reference)
#include <cuda_runtime.h>

#define XD 512
#define YD 384
#define LD 32
#define NPIX (XD * YD)

typedef unsigned long long ull;

__device__ float g_costs[9 * NPIX];
__device__ unsigned g_count;
__device__ int g_list[NPIX];

__device__ __forceinline__ float4 ld4(const float* p) { return *(const float4*)p; }

// ---- packed f32x2 helpers (sm_100+ PTX only; ptxas never emits these itself) ----
__device__ __forceinline__ ull f2pack(float lo, float hi) {
    ull r; asm("mov.b64 %0,{%1,%2};" : "=l"(r) : "f"(lo), "f"(hi)); return r;
}
__device__ __forceinline__ float2 f2unpack(ull v) {
    float lo, hi; asm("mov.b64 {%0,%1},%2;" : "=f"(lo), "=f"(hi) : "l"(v));
    return make_float2(lo, hi);
}
__device__ __forceinline__ ull f2mul(ull a, ull b) {
    ull r; asm("mul.rn.f32x2 %0,%1,%2;" : "=l"(r) : "l"(a), "l"(b)); return r;
}
__device__ __forceinline__ ull f2add(ull a, ull b) {
    ull r; asm("add.rn.f32x2 %0,%1,%2;" : "=l"(r) : "l"(a), "l"(b)); return r;
}
__device__ __forceinline__ ull f2fma(ull a, ull b, ull c) {
    ull r; asm("fma.rn.f32x2 %0,%1,%2,%3;" : "=l"(r) : "l"(a), "l"(b), "l"(c)); return r;
}
__device__ __forceinline__ float frcp(float x) {
    float r; asm("rcp.approx.ftz.f32 %0,%1;" : "=f"(r) : "f"(x)); return r;
}

// =================== Phase 0: reset fixup-list counter ===================
__global__ void zero_kernel() { g_count = 0u; }

// ======================= Phase 1: per-pixel 9 SSD costs (fast path only) ====
__global__ __launch_bounds__(256, 4)
void cost_kernel(const float* __restrict__ feat0,
                 const float* __restrict__ feat1,
                 const float* __restrict__ flow)
{
    const int tid  = threadIdx.x;
    const int wid  = tid >> 5;
    const int lane = tid & 31;
    const int g    = lane >> 3;   // pixel group within warp (0..3)
    const int sub  = lane & 7;    // channel chunk within pixel (0..7), 4 ch each
    const int bx   = blockIdx.x << 5;
    const int by   = blockIdx.y << 3;
    const int y    = by + wid;
    const float* f1s = feat1 + (sub << 2);

    // 1-deep software pipeline for the flow load
    const int pb0 = y * XD + bx + g;
    float u_nx = flow[pb0 * 3 + 0];
    float v_nx = flow[pb0 * 3 + 1];

    #pragma unroll 1
    for (int it = 0; it < 8; ++it) {
        const int lx    = (it << 2) + g;
        const int x     = bx + lx;
        const int pbase = y * XD + x;

        const float u = u_nx, v = v_nx;
        if (it < 7) {
            u_nx = flow[(pbase + 4) * 3 + 0];
            v_nx = flow[(pbase + 4) * 3 + 1];
        }

        const float px = (float)x + u;
        const float py = (float)y + v;

        // per-offset frac/floor, computed exactly like the reference
        float fx0, fx1, fx2, fy0, fy1, fy2;
        int ixm, ix0, ixp, iym, iy0, iyp;
        {
            float s, f;
            s = px - 1.0f; f = floorf(s); ixm = (int)f; fx0 = s - f;
            s = px;        f = floorf(s); ix0 = (int)f; fx1 = s - f;
            s = px + 1.0f; f = floorf(s); ixp = (int)f; fx2 = s - f;
            s = py - 1.0f; f = floorf(s); iym = (int)f; fy0 = s - f;
            s = py;        f = floorf(s); iy0 = (int)f; fy1 = s - f;
            s = py + 1.0f; f = floorf(s); iyp = (int)f; fy2 = s - f;
        }

        const float4 f0 = ld4(&feat0[pbase * LD + (sub << 2)]);

        const bool fast = (ixm == ix0 - 1) && (ixp == ix0 + 1)
                       && (iym == iy0 - 1) && (iyp == iy0 + 1)
                       && (ix0 >= 1) && (ix0 <= XD - 3)
                       && (iy0 >= 1) && (iy0 <= YD - 3);
        if (!fast && sub == 0) {
            const unsigned idx = atomicAdd(&g_count, 1u);
            g_list[idx] = pbase;   // exact recompute later in fixup_kernel
        }

        // clamped 4x4 window coords: identical to unclamped for fast pixels,
        // safe addresses otherwise (those pixels get overwritten by fixup)
        int cx[4], ry[4];
        #pragma unroll
        for (int i = 0; i < 4; i++) {
            int cc = ix0 - 1 + i; cx[i] = cc < 0 ? 0 : (cc > XD - 1 ? XD - 1 : cc);
            int rr = iy0 - 1 + i; ry[i] = rr < 0 ? 0 : (rr > YD - 1 ? YD - 1 : rr);
        }

        const ull FX0 = f2pack(fx0, fx0);
        const ull FX1 = f2pack(fx1, fx1);
        const ull FX2 = f2pack(fx2, fx2);
        const ull NEG1 = f2pack(-1.0f, -1.0f);
        const ull NF0 = f2pack(-f0.x, -f0.y);
        const ull NF1 = f2pack(-f0.z, -f0.w);
        const float fys[3] = {fy0, fy1, fy2};

        ull p0a, p0b, p1a, p1b, p2a, p2b;
        #pragma unroll
        for (int j = 0; j < 4; j++) {
            const float* rp = f1s + (ry[j] * XD) * LD;
            const ulonglong2 t0 = *(const ulonglong2*)(rp + cx[0] * LD);
            const ulonglong2 t1 = *(const ulonglong2*)(rp + cx[1] * LD);
            const ulonglong2 t2 = *(const ulonglong2*)(rp + cx[2] * LD);
            const ulonglong2 t3 = *(const ulonglong2*)(rp + cx[3] * LD);
            // h = t_left + fx * (t_right - t_left); sub via exact fma(-1,a,b)
            const ull h0a = f2fma(FX0, f2fma(NEG1, t0.x, t1.x), t0.x);
            const ull h0b = f2fma(FX0, f2fma(NEG1, t0.y, t1.y), t0.y);
            const ull h1a = f2fma(FX1, f2fma(NEG1, t1.x, t2.x), t1.x);
            const ull h1b = f2fma(FX1, f2fma(NEG1, t1.y, t2.y), t1.y);
            const ull h2a = f2fma(FX2, f2fma(NEG1, t2.x, t3.x), t2.x);
            const ull h2b = f2fma(FX2, f2fma(NEG1, t2.y, t3.y), t2.y);
            if (j > 0) {
                const float fy = fys[j - 1];
                const ull FY = f2pack(fy, fy);
                float c0, c1, c2;
                {
                    const ull sa = f2fma(FY, f2fma(NEG1, p0a, h0a), p0a);
                    const ull sb = f2fma(FY, f2fma(NEG1, p0b, h0b), p0b);
                    const ull da = f2add(sa, NF0), db = f2add(sb, NF1);
                    const float2 cu = f2unpack(f2fma(db, db, f2mul(da, da)));
                    c0 = cu.x + cu.y;
                }
                {
                    const ull sa = f2fma(FY, f2fma(NEG1, p1a, h1a), p1a);
                    const ull sb = f2fma(FY, f2fma(NEG1, p1b, h1b), p1b);
                    const ull da = f2add(sa, NF0), db = f2add(sb, NF1);
                    const float2 cu = f2unpack(f2fma(db, db, f2mul(da, da)));
                    c1 = cu.x + cu.y;
                }
                {
                    const ull sa = f2fma(FY, f2fma(NEG1, p2a, h2a), p2a);
                    const ull sb = f2fma(FY, f2fma(NEG1, p2b, h2b), p2b);
                    const ull da = f2add(sa, NF0), db = f2add(sb, NF1);
                    const float2 cu = f2unpack(f2fma(db, db, f2mul(da, da)));
                    c2 = cu.x + cu.y;
                }
                // early butterfly over the 8 lanes of this pixel group,
                // then lanes 0..2 store this row's 3 cost elements
                #pragma unroll
                for (int s = 1; s <= 4; s <<= 1) {
                    c0 += __shfl_xor_sync(0xffffffffu, c0, s);
                    c1 += __shfl_xor_sync(0xffffffffu, c1, s);
                    c2 += __shfl_xor_sync(0xffffffffu, c2, s);
                }
                const float cv = (sub == 0) ? c0 : ((sub == 1) ? c1 : c2);
                if (sub < 3)
                    g_costs[((j - 1) * 3 + sub) * NPIX + pbase] = cv;
            }
            p0a = h0a; p0b = h0b; p1a = h1a; p1b = h1b; p2a = h2a; p2b = h2b;
        }
    }
}

// ============ Phase 1b: exact recompute for listed (border) pixels ==========
__global__ __launch_bounds__(256, 2)
void fixup_kernel(const float* __restrict__ feat0,
                  const float* __restrict__ feat1,
                  const float* __restrict__ flow)
{
    const unsigned count = g_count;
    const int lane = threadIdx.x & 31;
    const int g    = lane >> 3;
    const int sub  = lane & 7;
    const unsigned warp  = (blockIdx.x * 256 + threadIdx.x) >> 5;
    const unsigned nslot = (gridDim.x * 256) >> 3;  // 4 slots per warp

    // warp-uniform grid-stride over list slots (4 pixels per warp per pass)
    for (unsigned base = warp * 4; base < count; base += nslot) {
        const unsigned slot = base + g;
        const bool valid = slot < count;
        const int pbase = valid ? g_list[slot] : 0;
        const int x = pbase & (XD - 1);
        const int y = pbase >> 9;

        const float u = flow[pbase * 3 + 0];
        const float v = flow[pbase * 3 + 1];
        const float px = (float)x + u;
        const float py = (float)y + v;

        float fxs[3], fys[3];
        int ixs[3], iys[3];
        {
            float s, f;
            s = px - 1.0f; f = floorf(s); ixs[0] = (int)f; fxs[0] = s - f;
            s = px;        f = floorf(s); ixs[1] = (int)f; fxs[1] = s - f;
            s = px + 1.0f; f = floorf(s); ixs[2] = (int)f; fxs[2] = s - f;
            s = py - 1.0f; f = floorf(s); iys[0] = (int)f; fys[0] = s - f;
            s = py;        f = floorf(s); iys[1] = (int)f; fys[1] = s - f;
            s = py + 1.0f; f = floorf(s); iys[2] = (int)f; fys[2] = s - f;
        }

        const float4 f0 = ld4(&feat0[pbase * LD + (sub << 2)]);

        // exact reference clamp protocol:
        //   t0 = clamp(floor(p), 0, D-1);  t1 = min(t0 + 1, D-1)
        int xs0[3], xs1[3], ys0[3], ys1[3];
        #pragma unroll
        for (int o = 0; o < 3; o++) {
            xs0[o] = min(max(ixs[o], 0), XD - 1);
            xs1[o] = min(xs0[o] + 1, XD - 1);
            ys0[o] = min(max(iys[o], 0), YD - 1);
            ys1[o] = min(ys0[o] + 1, YD - 1);
        }

        float c[9];
        #pragma unroll
        for (int p = 0; p < 3; p++) {
            #pragma unroll
            for (int o = 0; o < 3; o++) {
                const float wx = fxs[o], wy = fys[p];
                const float4 f00 = ld4(&feat1[(ys0[p] * XD + xs0[o]) * LD + (sub << 2)]);
                const float4 f01 = ld4(&feat1[(ys0[p] * XD + xs1[o]) * LD + (sub << 2)]);
                const float4 f10 = ld4(&feat1[(ys1[p] * XD + xs0[o]) * LD + (sub << 2)]);
                const float4 f11 = ld4(&feat1[(ys1[p] * XD + xs1[o]) * LD + (sub << 2)]);
                const float w00 = (1.0f - wx) * (1.0f - wy);
                const float w01 = wx * (1.0f - wy);
                const float w10 = (1.0f - wx) * wy;
                const float w11 = wx * wy;
                float4 s4;
                s4.x = fmaf(f00.x, w00, fmaf(f01.x, w01, fmaf(f10.x, w10, f11.x * w11)));
                s4.y = fmaf(f00.y, w00, fmaf(f01.y, w01, fmaf(f10.y, w10, f11.y * w11)));
                s4.z = fmaf(f00.z, w00, fmaf(f01.z, w01, fmaf(f10.z, w10, f11.z * w11)));
                s4.w = fmaf(f00.w, w00, fmaf(f01.w, w01, fmaf(f10.w, w10, f11.w * w11)));
                const float dx = s4.x - f0.x, dy = s4.y - f0.y;
                const float dz = s4.z - f0.z, dw = s4.w - f0.w;
                c[p * 3 + o] = fmaf(dx, dx, fmaf(dy, dy, fmaf(dz, dz, dw * dw)));
            }
        }

        #pragma unroll
        for (int k = 0; k < 9; k++) {
            c[k] += __shfl_xor_sync(0xffffffffu, c[k], 1);
            c[k] += __shfl_xor_sync(0xffffffffu, c[k], 2);
            c[k] += __shfl_xor_sync(0xffffffffu, c[k], 4);
        }
        if (valid) {
            g_costs[sub * NPIX + pbase] = c[sub];
            if (sub == 0) g_costs[8 * NPIX + pbase] = c[8];
        }
    }
}

// ======================= Phase 2: softmax + WLS solve =======================
__device__ __forceinline__ constexpr int tix(int i, int j) { return i * (i + 1) / 2 + j; }

__device__ __forceinline__ void ldlt_solve(const float* __restrict__ m,
                                           const float* __restrict__ dinv,
                                           float* __restrict__ r)
{
    #pragma unroll
    for (int i = 1; i < 6; i++) {
        #pragma unroll
        for (int k = 0; k < i; k++) r[i] -= m[tix(i, k)] * r[k];
    }
    #pragma unroll
    for (int i = 0; i < 6; i++) r[i] *= dinv[i];
    #pragma unroll
    for (int i = 4; i >= 0; i--) {
        #pragma unroll
        for (int k = i + 1; k < 6; k++) r[i] -= m[tix(k, i)] * r[k];
    }
}

__global__ __launch_bounds__(256, 4)
void solve_kernel(float* __restrict__ out)
{
    const int gid = blockIdx.x * 256 + threadIdx.x;

    float c[9];
    #pragma unroll
    for (int k = 0; k < 9; k++) c[k] = g_costs[k * NPIX + gid];  // coalesced

    float cmin = c[0];
    #pragma unroll
    for (int k = 1; k < 9; k++) cmin = fminf(cmin, c[k]);

    float e[9], S = 0.0f;
    #pragma unroll
    for (int k = 0; k < 9; k++) { e[k] = __expf(cmin - c[k]); S += e[k]; }
    const float inv = 1.0f / S;

    float w[9], q[9];
    #pragma unroll
    for (int k = 0; k < 9; k++) { w[k] = e[k] * inv; q[k] = w[k] * c[k]; }

    // moments of w over {-1,0,1}^2 (x^4=x^2, x^3=x fold)
    const float S20 = w[0] + w[2] + w[3] + w[5] + w[6] + w[8];
    const float S02 = w[0] + w[1] + w[2] + w[6] + w[7] + w[8];
    const float S11 = ((w[0] - w[2]) - w[6]) + w[8];
    const float S10 = ((((-w[0] + w[2]) - w[3]) + w[5]) - w[6]) + w[8];
    const float S01 = ((-w[0] - w[1]) - w[2]) + w[6] + w[7] + w[8];
    const float S21 = ((-w[0] - w[2]) + w[6]) + w[8];
    const float S12 = ((-w[0] + w[2]) - w[6]) + w[8];
    const float S22 = w[0] + w[2] + w[6] + w[8];
    const float S00 = ((((((w[0] + w[1]) + w[2]) + w[3]) + w[4] + w[5]) + w[6]) + w[7]) + w[8];

    const float E = 1e-4f;
    const float a00 = S20 + E, a11 = S02 + E, a22 = S22 + E;
    const float a33 = S20 + E, a44 = S02 + E, a55 = S00 + E;

    float b[6];
    b[0] = q[0] + q[2] + q[3] + q[5] + q[6] + q[8];
    b[1] = q[0] + q[1] + q[2] + q[6] + q[7] + q[8];
    b[2] = ((q[0] - q[2]) - q[6]) + q[8];
    b[3] = ((((-q[0] + q[2]) - q[3]) + q[5]) - q[6]) + q[8];
    b[4] = ((-q[0] - q[1]) - q[2]) + q[6] + q[7] + q[8];
    b[5] = ((((((q[0] + q[1]) + q[2]) + q[3]) + q[4] + q[5]) + q[6]) + q[7]) + q[8];

    float m[21];
    m[tix(0,0)] = a00;
    m[tix(1,0)] = S22; m[tix(1,1)] = a11;
    m[tix(2,0)] = S11; m[tix(2,1)] = S11; m[tix(2,2)] = a22;
    m[tix(3,0)] = S10; m[tix(3,1)] = S12; m[tix(3,2)] = S21; m[tix(3,3)] = a33;
    m[tix(4,0)] = S21; m[tix(4,1)] = S01; m[tix(4,2)] = S12; m[tix(4,3)] = S11; m[tix(4,4)] = a44;
    m[tix(5,0)] = S20; m[tix(5,1)] = S02; m[tix(5,2)] = S11; m[tix(5,3)] = S10; m[tix(5,4)] = S01; m[tix(5,5)] = a55;

    float dinv[6];
    #pragma unroll
    for (int j = 0; j < 6; j++) {
        float d = m[tix(j, j)];
        #pragma unroll
        for (int k = 0; k < j; k++) d -= m[tix(j, k)] * m[tix(j, k)] * m[tix(k, k)];
        m[tix(j, j)] = d;
        const float id = frcp(d);
        dinv[j] = id;
        #pragma unroll
        for (int i = j + 1; i < 6; i++) {
            float s = m[tix(i, j)];
            #pragma unroll
            for (int k = 0; k < j; k++) s -= m[tix(i, k)] * m[tix(j, k)] * m[tix(k, k)];
            m[tix(i, j)] = s * id;
        }
    }

    float x[6];
    #pragma unroll
    for (int i = 0; i < 6; i++) x[i] = b[i];
    ldlt_solve(m, dinv, x);

    // one step of iterative refinement: residual via exact TwoProd/TwoSum
    const float Arow[6][6] = {
        { a00, S22, S11, S10, S21, S20 },
        { S22, a11, S11, S12, S01, S02 },
        { S11, S11, a22, S21, S12, S11 },
        { S10, S12, S21, a33, S11, S10 },
        { S21, S01, S12, S11, a44, S01 },
        { S20, S02, S11, S10, S01, a55 }
    };
    float r[6];
    #pragma unroll
    for (int i = 0; i < 6; i++) {
        float s = b[i], t = 0.0f;
        #pragma unroll
        for (int j = 0; j < 6; j++) {
            const float aij = Arow[i][j];
            const float p  = aij * x[j];
            const float ep = fmaf(aij, x[j], -p);   // exact product error
            const float a2 = -p;                    // TwoSum(s, -p)
            const float s2 = s + a2;
            const float vv = s2 - s;
            const float es = (s - (s2 - vv)) + (a2 - vv);
            s = s2;
            t += es - ep;
        }
        r[i] = s + t;
    }
    ldlt_solve(m, dinv, r);
    #pragma unroll
    for (int i = 0; i < 6; i++) x[i] += r[i];

    float* op = &out[gid * 6];
    #pragma unroll
    for (int i = 0; i < 6; i++) op[i] = x[i];
}

extern "C" void kernel_launch(void* const* d_in, const int* in_sizes, int n_in,
                              void* d_out, int out_size) {
    (void)in_sizes; (void)n_in; (void)out_size;
    const float* feat0 = (const float*)d_in[0];
    const float* feat1 = (const float*)d_in[1];
    const float* flow  = (const float*)d_in[2];
    float* out = (float*)d_out;
    dim3 grid1(XD / 32, YD / 8);
    zero_kernel<<<1, 1>>>();
    cost_kernel<<<grid1, 256>>>(feat0, feat1, flow);
    fixup_kernel<<<128, 256>>>(feat0, feat1, flow);
    solve_kernel<<<NPIX / 256, 256>>>(out);
}

// round 14
// speedup vs baseline: 1.0346x; 1.0346x over previous
#include <cuda_runtime.h>

#define XD 512
#define YD 384
#define LD 32
#define NPIX (XD * YD)

typedef unsigned long long ull;

__device__ float g_costs[9 * NPIX];

__device__ __forceinline__ float4 ld4(const float* p) { return *(const float4*)p; }

// streaming loads/stores: L2-only (.cg), keep L1 reserved for feat1 taps
__device__ __forceinline__ float ldcg(const float* p) {
    float r; asm("ld.global.cg.f32 %0,[%1];" : "=f"(r) : "l"(p)); return r;
}
__device__ __forceinline__ float4 ldcg4(const float* p) {
    float4 r;
    asm("ld.global.cg.v4.f32 {%0,%1,%2,%3},[%4];"
        : "=f"(r.x), "=f"(r.y), "=f"(r.z), "=f"(r.w) : "l"(p));
    return r;
}
__device__ __forceinline__ void stcg(float* p, float v) {
    asm("st.global.cg.f32 [%0],%1;" :: "l"(p), "f"(v));
}

// ---- packed f32x2 helpers (sm_100+ PTX only; ptxas never emits these itself) ----
__device__ __forceinline__ ull f2pack(float lo, float hi) {
    ull r; asm("mov.b64 %0,{%1,%2};" : "=l"(r) : "f"(lo), "f"(hi)); return r;
}
__device__ __forceinline__ float2 f2unpack(ull v) {
    float lo, hi; asm("mov.b64 {%0,%1},%2;" : "=f"(lo), "=f"(hi) : "l"(v));
    return make_float2(lo, hi);
}
__device__ __forceinline__ ull f2mul(ull a, ull b) {
    ull r; asm("mul.rn.f32x2 %0,%1,%2;" : "=l"(r) : "l"(a), "l"(b)); return r;
}
__device__ __forceinline__ ull f2add(ull a, ull b) {
    ull r; asm("add.rn.f32x2 %0,%1,%2;" : "=l"(r) : "l"(a), "l"(b)); return r;
}
__device__ __forceinline__ ull f2fma(ull a, ull b, ull c) {
    ull r; asm("fma.rn.f32x2 %0,%1,%2,%3;" : "=l"(r) : "l"(a), "l"(b), "l"(c)); return r;
}
__device__ __forceinline__ float frcp(float x) {
    float r; asm("rcp.approx.ftz.f32 %0,%1;" : "=f"(r) : "f"(x)); return r;
}

// ======================= Phase 1: per-pixel 9 SSD costs =======================
__global__ __launch_bounds__(256, 2)
void cost_kernel(const float* __restrict__ feat0,
                 const float* __restrict__ feat1,
                 const float* __restrict__ flow)
{
    const int tid  = threadIdx.x;
    const int wid  = tid >> 5;
    const int lane = tid & 31;
    const int g    = lane >> 3;   // pixel group within warp (0..3)
    const int sub  = lane & 7;    // channel chunk within pixel (0..7), 4 ch each
    const int bx   = blockIdx.x << 5;
    const int by   = blockIdx.y << 3;
    const int y    = by + wid;

    // prefetch all 8 flow (u,v) pairs up front (L2-only loads)
    float uu[8], vv[8];
    #pragma unroll
    for (int it = 0; it < 8; ++it) {
        const int pb = y * XD + bx + (it << 2) + g;
        uu[it] = ldcg(&flow[pb * 3 + 0]);
        vv[it] = ldcg(&flow[pb * 3 + 1]);
    }

    #pragma unroll 2
    for (int it = 0; it < 8; ++it) {
        const int lx    = (it << 2) + g;
        const int x     = bx + lx;
        const int pbase = y * XD + x;

        const float px = (float)x + uu[it];
        const float py = (float)y + vv[it];

        // per-offset frac/floor, computed exactly like the reference
        float fx0, fx1, fx2, fy0, fy1, fy2;
        int ixm, ix0, ixp, iym, iy0, iyp;
        {
            float s, f;
            s = px - 1.0f; f = floorf(s); ixm = (int)f; fx0 = s - f;
            s = px;        f = floorf(s); ix0 = (int)f; fx1 = s - f;
            s = px + 1.0f; f = floorf(s); ixp = (int)f; fx2 = s - f;
            s = py - 1.0f; f = floorf(s); iym = (int)f; fy0 = s - f;
            s = py;        f = floorf(s); iy0 = (int)f; fy1 = s - f;
            s = py + 1.0f; f = floorf(s); iyp = (int)f; fy2 = s - f;
        }

        const float4 f0 = ldcg4(&feat0[pbase * LD + (sub << 2)]);
        float c[9];

        // fast path: floors consistent AND the full 4x4 tap window interior
        const bool fast = (ixm == ix0 - 1) && (ixp == ix0 + 1)
                       && (iym == iy0 - 1) && (iyp == iy0 + 1)
                       && (ix0 >= 1) && (ix0 <= XD - 3)
                       && (iy0 >= 1) && (iy0 <= YD - 3);
        if (fast) {
            // packed f32x2: each thread handles 4 channels = 2 packed lanes
            const ull WX0 = f2pack(fx0, fx0), MX0 = f2pack(1.0f - fx0, 1.0f - fx0);
            const ull WX1 = f2pack(fx1, fx1), MX1 = f2pack(1.0f - fx1, 1.0f - fx1);
            const ull WX2 = f2pack(fx2, fx2), MX2 = f2pack(1.0f - fx2, 1.0f - fx2);
            const ull NF0 = f2pack(-f0.x, -f0.y);
            const ull NF1 = f2pack(-f0.z, -f0.w);
            const float fys[3] = {fy0, fy1, fy2};

            ull p0a, p0b, p1a, p1b, p2a, p2b;
            #pragma unroll
            for (int j = 0; j < 4; j++) {
                const float* rp = &feat1[((iy0 - 1 + j) * XD + (ix0 - 1)) * LD + (sub << 2)];
                const ulonglong2 t0 = *(const ulonglong2*)(rp);
                const ulonglong2 t1 = *(const ulonglong2*)(rp + LD);
                const ulonglong2 t2 = *(const ulonglong2*)(rp + 2 * LD);
                const ulonglong2 t3 = *(const ulonglong2*)(rp + 3 * LD);
                // horizontal lerps: h = (1-fx)*left + fx*right
                const ull h0a = f2fma(WX0, t1.x, f2mul(MX0, t0.x));
                const ull h0b = f2fma(WX0, t1.y, f2mul(MX0, t0.y));
                const ull h1a = f2fma(WX1, t2.x, f2mul(MX1, t1.x));
                const ull h1b = f2fma(WX1, t2.y, f2mul(MX1, t1.y));
                const ull h2a = f2fma(WX2, t3.x, f2mul(MX2, t2.x));
                const ull h2b = f2fma(WX2, t3.y, f2mul(MX2, t2.y));
                if (j > 0) {
                    const float fy = fys[j - 1];
                    const ull WY = f2pack(fy, fy), MY = f2pack(1.0f - fy, 1.0f - fy);
                    {   // sample column 0
                        const ull sa = f2fma(WY, h0a, f2mul(MY, p0a));
                        const ull sb = f2fma(WY, h0b, f2mul(MY, p0b));
                        const ull da = f2add(sa, NF0), db = f2add(sb, NF1);
                        const float2 cu = f2unpack(f2fma(db, db, f2mul(da, da)));
                        c[(j - 1) * 3 + 0] = cu.x + cu.y;
                    }
                    {   // sample column 1
                        const ull sa = f2fma(WY, h1a, f2mul(MY, p1a));
                        const ull sb = f2fma(WY, h1b, f2mul(MY, p1b));
                        const ull da = f2add(sa, NF0), db = f2add(sb, NF1);
                        const float2 cu = f2unpack(f2fma(db, db, f2mul(da, da)));
                        c[(j - 1) * 3 + 1] = cu.x + cu.y;
                    }
                    {   // sample column 2
                        const ull sa = f2fma(WY, h2a, f2mul(MY, p2a));
                        const ull sb = f2fma(WY, h2b, f2mul(MY, p2b));
                        const ull da = f2add(sa, NF0), db = f2add(sb, NF1);
                        const float2 cu = f2unpack(f2fma(db, db, f2mul(da, da)));
                        c[(j - 1) * 3 + 2] = cu.x + cu.y;
                    }
                }
                p0a = h0a; p0b = h0b; p1a = h1a; p1b = h1b; p2a = h2a; p2b = h2b;
            }
        } else {
            // exact reference clamp protocol (border pixels):
            //   t0 = clamp(floor(p), 0, D-1);  t1 = min(t0 + 1, D-1)
            const int   ixs[3] = {ixm, ix0, ixp};
            const int   iys[3] = {iym, iy0, iyp};
            const float fxs[3] = {fx0, fx1, fx2};
            const float fys[3] = {fy0, fy1, fy2};
            int xs0[3], xs1[3], ys0[3], ys1[3];
            #pragma unroll
            for (int o = 0; o < 3; o++) {
                xs0[o] = min(max(ixs[o], 0), XD - 1);
                xs1[o] = min(xs0[o] + 1, XD - 1);
                ys0[o] = min(max(iys[o], 0), YD - 1);
                ys1[o] = min(ys0[o] + 1, YD - 1);
            }
            #pragma unroll
            for (int p = 0; p < 3; p++) {
                #pragma unroll
                for (int o = 0; o < 3; o++) {
                    const float wx = fxs[o], wy = fys[p];
                    const float4 f00 = ld4(&feat1[(ys0[p] * XD + xs0[o]) * LD + (sub << 2)]);
                    const float4 f01 = ld4(&feat1[(ys0[p] * XD + xs1[o]) * LD + (sub << 2)]);
                    const float4 f10 = ld4(&feat1[(ys1[p] * XD + xs0[o]) * LD + (sub << 2)]);
                    const float4 f11 = ld4(&feat1[(ys1[p] * XD + xs1[o]) * LD + (sub << 2)]);
                    const float w00 = (1.0f - wx) * (1.0f - wy);
                    const float w01 = wx * (1.0f - wy);
                    const float w10 = (1.0f - wx) * wy;
                    const float w11 = wx * wy;
                    float4 s4;
                    s4.x = fmaf(f00.x, w00, fmaf(f01.x, w01, fmaf(f10.x, w10, f11.x * w11)));
                    s4.y = fmaf(f00.y, w00, fmaf(f01.y, w01, fmaf(f10.y, w10, f11.y * w11)));
                    s4.z = fmaf(f00.z, w00, fmaf(f01.z, w01, fmaf(f10.z, w10, f11.z * w11)));
                    s4.w = fmaf(f00.w, w00, fmaf(f01.w, w01, fmaf(f10.w, w10, f11.w * w11)));
                    const float dx = s4.x - f0.x, dy = s4.y - f0.y;
                    const float dz = s4.z - f0.z, dw = s4.w - f0.w;
                    c[p * 3 + o] = fmaf(dx, dx, fmaf(dy, dy, fmaf(dz, dz, dw * dw)));
                }
            }
        }

        // butterfly reduce over the 8 lanes of this pixel group
        #pragma unroll
        for (int k = 0; k < 9; k++) {
            c[k] += __shfl_xor_sync(0xffffffffu, c[k], 1);
            c[k] += __shfl_xor_sync(0xffffffffu, c[k], 2);
            c[k] += __shfl_xor_sync(0xffffffffu, c[k], 4);
        }
        stcg(&g_costs[sub * NPIX + pbase], c[sub]);
        if (sub == 0) stcg(&g_costs[8 * NPIX + pbase], c[8]);
    }
}

// ======================= Phase 2: softmax + WLS solve =======================
__device__ __forceinline__ constexpr int tix(int i, int j) { return i * (i + 1) / 2 + j; }

// forward/diag/back substitution with LDL^T factors in m[21], dinv[6]
__device__ __forceinline__ void ldlt_solve(const float* __restrict__ m,
                                           const float* __restrict__ dinv,
                                           float* __restrict__ r)
{
    #pragma unroll
    for (int i = 1; i < 6; i++) {
        #pragma unroll
        for (int k = 0; k < i; k++) r[i] -= m[tix(i, k)] * r[k];
    }
    #pragma unroll
    for (int i = 0; i < 6; i++) r[i] *= dinv[i];
    #pragma unroll
    for (int i = 4; i >= 0; i--) {
        #pragma unroll
        for (int k = i + 1; k < 6; k++) r[i] -= m[tix(k, i)] * r[k];
    }
}

__global__ __launch_bounds__(256, 4)
void solve_kernel(float* __restrict__ out)
{
    const int gid = blockIdx.x * 256 + threadIdx.x;

    float c[9];
    #pragma unroll
    for (int k = 0; k < 9; k++) c[k] = g_costs[k * NPIX + gid];  // coalesced

    float cmin = c[0];
    #pragma unroll
    for (int k = 1; k < 9; k++) cmin = fminf(cmin, c[k]);

    float e[9], S = 0.0f;
    #pragma unroll
    for (int k = 0; k < 9; k++) { e[k] = __expf(cmin - c[k]); S += e[k]; }
    const float inv = 1.0f / S;

    float w[9], q[9];
    #pragma unroll
    for (int k = 0; k < 9; k++) { w[k] = e[k] * inv; q[k] = w[k] * c[k]; }

    // moments of w over {-1,0,1}^2 (x^4=x^2, x^3=x fold)
    const float S20 = w[0] + w[2] + w[3] + w[5] + w[6] + w[8];
    const float S02 = w[0] + w[1] + w[2] + w[6] + w[7] + w[8];
    const float S11 = ((w[0] - w[2]) - w[6]) + w[8];
    const float S10 = ((((-w[0] + w[2]) - w[3]) + w[5]) - w[6]) + w[8];
    const float S01 = ((-w[0] - w[1]) - w[2]) + w[6] + w[7] + w[8];
    const float S21 = ((-w[0] - w[2]) + w[6]) + w[8];
    const float S12 = ((-w[0] + w[2]) - w[6]) + w[8];
    const float S22 = w[0] + w[2] + w[6] + w[8];
    const float S00 = ((((((w[0] + w[1]) + w[2]) + w[3]) + w[4] + w[5]) + w[6]) + w[7]) + w[8];

    const float E = 1e-4f;
    const float a00 = S20 + E, a11 = S02 + E, a22 = S22 + E;
    const float a33 = S20 + E, a44 = S02 + E, a55 = S00 + E;

    float b[6];
    b[0] = q[0] + q[2] + q[3] + q[5] + q[6] + q[8];
    b[1] = q[0] + q[1] + q[2] + q[6] + q[7] + q[8];
    b[2] = ((q[0] - q[2]) - q[6]) + q[8];
    b[3] = ((((-q[0] + q[2]) - q[3]) + q[5]) - q[6]) + q[8];
    b[4] = ((-q[0] - q[1]) - q[2]) + q[6] + q[7] + q[8];
    b[5] = ((((((q[0] + q[1]) + q[2]) + q[3]) + q[4] + q[5]) + q[6]) + q[7]) + q[8];

    // pack symmetric lower triangle, factor LDL^T in place (fp32)
    float m[21];
    m[tix(0,0)] = a00;
    m[tix(1,0)] = S22; m[tix(1,1)] = a11;
    m[tix(2,0)] = S11; m[tix(2,1)] = S11; m[tix(2,2)] = a22;
    m[tix(3,0)] = S10; m[tix(3,1)] = S12; m[tix(3,2)] = S21; m[tix(3,3)] = a33;
    m[tix(4,0)] = S21; m[tix(4,1)] = S01; m[tix(4,2)] = S12; m[tix(4,3)] = S11; m[tix(4,4)] = a44;
    m[tix(5,0)] = S20; m[tix(5,1)] = S02; m[tix(5,2)] = S11; m[tix(5,3)] = S10; m[tix(5,4)] = S01; m[tix(5,5)] = a55;

    // approx reciprocals are fine here: the compensated refinement step below
    // corrects any preconditioner error
    float dinv[6];
    #pragma unroll
    for (int j = 0; j < 6; j++) {
        float d = m[tix(j, j)];
        #pragma unroll
        for (int k = 0; k < j; k++) d -= m[tix(j, k)] * m[tix(j, k)] * m[tix(k, k)];
        m[tix(j, j)] = d;
        const float id = frcp(d);
        dinv[j] = id;
        #pragma unroll
        for (int i = j + 1; i < 6; i++) {
            float s = m[tix(i, j)];
            #pragma unroll
            for (int k = 0; k < j; k++) s -= m[tix(i, k)] * m[tix(j, k)] * m[tix(k, k)];
            m[tix(i, j)] = s * id;
        }
    }

    float x[6];
    #pragma unroll
    for (int i = 0; i < 6; i++) x[i] = b[i];
    ldlt_solve(m, dinv, x);

    // one step of iterative refinement: residual via exact TwoProd/TwoSum
    // (all-fp32 compensated arithmetic; no fp64 anywhere)
    const float Arow[6][6] = {
        { a00, S22, S11, S10, S21, S20 },
        { S22, a11, S11, S12, S01, S02 },
        { S11, S11, a22, S21, S12, S11 },
        { S10, S12, S21, a33, S11, S10 },
        { S21, S01, S12, S11, a44, S01 },
        { S20, S02, S11, S10, S01, a55 }
    };
    float r[6];
    #pragma unroll
    for (int i = 0; i < 6; i++) {
        float s = b[i], t = 0.0f;
        #pragma unroll
        for (int j = 0; j < 6; j++) {
            const float aij = Arow[i][j];
            const float p  = aij * x[j];
            const float ep = fmaf(aij, x[j], -p);   // exact product error
            const float a2 = -p;                    // TwoSum(s, -p)
            const float s2 = s + a2;
            const float v  = s2 - s;
            const float es = (s - (s2 - v)) + (a2 - v);
            s = s2;
            t += es - ep;
        }
        r[i] = s + t;
    }
    ldlt_solve(m, dinv, r);
    #pragma unroll
    for (int i = 0; i < 6; i++) x[i] += r[i];

    float* op = &out[gid * 6];
    #pragma unroll
    for (int i = 0; i < 6; i++) op[i] = x[i];
}

extern "C" void kernel_launch(void* const* d_in, const int* in_sizes, int n_in,
                              void* d_out, int out_size) {
    (void)in_sizes; (void)n_in; (void)out_size;
    const float* feat0 = (const float*)d_in[0];
    const float* feat1 = (const float*)d_in[1];
    const float* flow  = (const float*)d_in[2];
    float* out = (float*)d_out;
    dim3 grid1(XD / 32, YD / 8);
    cost_kernel<<<grid1, 256>>>(feat0, feat1, flow);
    solve_kernel<<<NPIX / 256, 256>>>(out);
}

// round 16
// speedup vs baseline: 1.1876x; 1.1479x over previous
#include <cuda_runtime.h>

#define XD 512
#define YD 384
#define LD 32
#define NPIX (XD * YD)

typedef unsigned long long ull;

__device__ float g_costs[9 * NPIX];

__device__ __forceinline__ float4 ld4(const float* p) { return *(const float4*)p; }

// ---- packed f32x2 helpers (sm_100+ PTX only; ptxas never emits these itself) ----
__device__ __forceinline__ ull f2pack(float lo, float hi) {
    ull r; asm("mov.b64 %0,{%1,%2};" : "=l"(r) : "f"(lo), "f"(hi)); return r;
}
__device__ __forceinline__ float2 f2unpack(ull v) {
    float lo, hi; asm("mov.b64 {%0,%1},%2;" : "=f"(lo), "=f"(hi) : "l"(v));
    return make_float2(lo, hi);
}
__device__ __forceinline__ ull f2mul(ull a, ull b) {
    ull r; asm("mul.rn.f32x2 %0,%1,%2;" : "=l"(r) : "l"(a), "l"(b)); return r;
}
__device__ __forceinline__ ull f2add(ull a, ull b) {
    ull r; asm("add.rn.f32x2 %0,%1,%2;" : "=l"(r) : "l"(a), "l"(b)); return r;
}
__device__ __forceinline__ ull f2fma(ull a, ull b, ull c) {
    ull r; asm("fma.rn.f32x2 %0,%1,%2,%3;" : "=l"(r) : "l"(a), "l"(b), "l"(c)); return r;
}
__device__ __forceinline__ float frcp(float x) {
    float r; asm("rcp.approx.ftz.f32 %0,%1;" : "=f"(r) : "f"(x)); return r;
}

// ======================= Phase 1: per-pixel 9 SSD costs =======================
__global__ __launch_bounds__(256, 3)
void cost_kernel(const float* __restrict__ feat0,
                 const float* __restrict__ feat1,
                 const float* __restrict__ flow)
{
    const int tid  = threadIdx.x;
    const int wid  = tid >> 5;
    const int lane = tid & 31;
    const int g    = lane >> 3;   // pixel group within warp (0..3)
    const int sub  = lane & 7;    // channel chunk within pixel (0..7), 4 ch each
    const int bx   = blockIdx.x << 5;
    const int by   = blockIdx.y << 3;
    const int y    = by + wid;
    const bool h4  = (sub & 4) != 0;
    const bool h2  = (sub & 2) != 0;
    const bool h1  = (sub & 1) != 0;

    // prefetch all 8 flow (u,v) pairs up front: 16 independent loads
    float uu[8], vv[8];
    #pragma unroll
    for (int it = 0; it < 8; ++it) {
        const int pb = y * XD + bx + (it << 2) + g;
        uu[it] = flow[pb * 3 + 0];
        vv[it] = flow[pb * 3 + 1];
    }

    #pragma unroll 2
    for (int it = 0; it < 8; ++it) {
        const int lx    = (it << 2) + g;
        const int x     = bx + lx;
        const int pbase = y * XD + x;

        const float px = (float)x + uu[it];
        const float py = (float)y + vv[it];

        // per-offset frac/floor, computed exactly like the reference
        float fx0, fx1, fx2, fy0, fy1, fy2;
        int ixm, ix0, ixp, iym, iy0, iyp;
        {
            float s, f;
            s = px - 1.0f; f = floorf(s); ixm = (int)f; fx0 = s - f;
            s = px;        f = floorf(s); ix0 = (int)f; fx1 = s - f;
            s = px + 1.0f; f = floorf(s); ixp = (int)f; fx2 = s - f;
            s = py - 1.0f; f = floorf(s); iym = (int)f; fy0 = s - f;
            s = py;        f = floorf(s); iy0 = (int)f; fy1 = s - f;
            s = py + 1.0f; f = floorf(s); iyp = (int)f; fy2 = s - f;
        }

        const float4 f0 = ld4(&feat0[pbase * LD + (sub << 2)]);
        float c[9];

        // fast path: floors consistent AND the full 4x4 tap window interior
        const bool fast = (ixm == ix0 - 1) && (ixp == ix0 + 1)
                       && (iym == iy0 - 1) && (iyp == iy0 + 1)
                       && (ix0 >= 1) && (ix0 <= XD - 3)
                       && (iy0 >= 1) && (iy0 <= YD - 3);
        if (fast) {
            // packed f32x2: each thread handles 4 channels = 2 packed lanes
            const ull WX0 = f2pack(fx0, fx0), MX0 = f2pack(1.0f - fx0, 1.0f - fx0);
            const ull WX1 = f2pack(fx1, fx1), MX1 = f2pack(1.0f - fx1, 1.0f - fx1);
            const ull WX2 = f2pack(fx2, fx2), MX2 = f2pack(1.0f - fx2, 1.0f - fx2);
            const ull NF0 = f2pack(-f0.x, -f0.y);
            const ull NF1 = f2pack(-f0.z, -f0.w);
            const float fys[3] = {fy0, fy1, fy2};

            ull p0a, p0b, p1a, p1b, p2a, p2b;
            #pragma unroll
            for (int j = 0; j < 4; j++) {
                const float* rp = &feat1[((iy0 - 1 + j) * XD + (ix0 - 1)) * LD + (sub << 2)];
                const ulonglong2 t0 = *(const ulonglong2*)(rp);
                const ulonglong2 t1 = *(const ulonglong2*)(rp + LD);
                const ulonglong2 t2 = *(const ulonglong2*)(rp + 2 * LD);
                const ulonglong2 t3 = *(const ulonglong2*)(rp + 3 * LD);
                // horizontal lerps: h = (1-fx)*left + fx*right
                const ull h0a = f2fma(WX0, t1.x, f2mul(MX0, t0.x));
                const ull h0b = f2fma(WX0, t1.y, f2mul(MX0, t0.y));
                const ull h1a = f2fma(WX1, t2.x, f2mul(MX1, t1.x));
                const ull h1b = f2fma(WX1, t2.y, f2mul(MX1, t1.y));
                const ull h2a = f2fma(WX2, t3.x, f2mul(MX2, t2.x));
                const ull h2b = f2fma(WX2, t3.y, f2mul(MX2, t2.y));
                if (j > 0) {
                    const float fy = fys[j - 1];
                    const ull WY = f2pack(fy, fy), MY = f2pack(1.0f - fy, 1.0f - fy);
                    {   // sample column 0
                        const ull sa = f2fma(WY, h0a, f2mul(MY, p0a));
                        const ull sb = f2fma(WY, h0b, f2mul(MY, p0b));
                        const ull da = f2add(sa, NF0), db = f2add(sb, NF1);
                        const float2 cu = f2unpack(f2fma(db, db, f2mul(da, da)));
                        c[(j - 1) * 3 + 0] = cu.x + cu.y;
                    }
                    {   // sample column 1
                        const ull sa = f2fma(WY, h1a, f2mul(MY, p1a));
                        const ull sb = f2fma(WY, h1b, f2mul(MY, p1b));
                        const ull da = f2add(sa, NF0), db = f2add(sb, NF1);
                        const float2 cu = f2unpack(f2fma(db, db, f2mul(da, da)));
                        c[(j - 1) * 3 + 1] = cu.x + cu.y;
                    }
                    {   // sample column 2
                        const ull sa = f2fma(WY, h2a, f2mul(MY, p2a));
                        const ull sb = f2fma(WY, h2b, f2mul(MY, p2b));
                        const ull da = f2add(sa, NF0), db = f2add(sb, NF1);
                        const float2 cu = f2unpack(f2fma(db, db, f2mul(da, da)));
                        c[(j - 1) * 3 + 2] = cu.x + cu.y;
                    }
                }
                p0a = h0a; p0b = h0b; p1a = h1a; p1b = h1b; p2a = h2a; p2b = h2b;
            }
        } else {
            // exact reference clamp protocol (border pixels):
            //   t0 = clamp(floor(p), 0, D-1);  t1 = min(t0 + 1, D-1)
            const int   ixs[3] = {ixm, ix0, ixp};
            const int   iys[3] = {iym, iy0, iyp};
            const float fxs[3] = {fx0, fx1, fx2};
            const float fys[3] = {fy0, fy1, fy2};
            int xs0[3], xs1[3], ys0[3], ys1[3];
            #pragma unroll
            for (int o = 0; o < 3; o++) {
                xs0[o] = min(max(ixs[o], 0), XD - 1);
                xs1[o] = min(xs0[o] + 1, XD - 1);
                ys0[o] = min(max(iys[o], 0), YD - 1);
                ys1[o] = min(ys0[o] + 1, YD - 1);
            }
            #pragma unroll
            for (int p = 0; p < 3; p++) {
                #pragma unroll
                for (int o = 0; o < 3; o++) {
                    const float wx = fxs[o], wy = fys[p];
                    const float4 f00 = ld4(&feat1[(ys0[p] * XD + xs0[o]) * LD + (sub << 2)]);
                    const float4 f01 = ld4(&feat1[(ys0[p] * XD + xs1[o]) * LD + (sub << 2)]);
                    const float4 f10 = ld4(&feat1[(ys1[p] * XD + xs0[o]) * LD + (sub << 2)]);
                    const float4 f11 = ld4(&feat1[(ys1[p] * XD + xs1[o]) * LD + (sub << 2)]);
                    const float w00 = (1.0f - wx) * (1.0f - wy);
                    const float w01 = wx * (1.0f - wy);
                    const float w10 = (1.0f - wx) * wy;
                    const float w11 = wx * wy;
                    float4 s4;
                    s4.x = fmaf(f00.x, w00, fmaf(f01.x, w01, fmaf(f10.x, w10, f11.x * w11)));
                    s4.y = fmaf(f00.y, w00, fmaf(f01.y, w01, fmaf(f10.y, w10, f11.y * w11)));
                    s4.z = fmaf(f00.z, w00, fmaf(f01.z, w01, fmaf(f10.z, w10, f11.z * w11)));
                    s4.w = fmaf(f00.w, w00, fmaf(f01.w, w01, fmaf(f10.w, w10, f11.w * w11)));
                    const float dx = s4.x - f0.x, dy = s4.y - f0.y;
                    const float dz = s4.z - f0.z, dw = s4.w - f0.w;
                    c[p * 3 + o] = fmaf(dx, dx, fmaf(dy, dy, fmaf(dz, dz, dw * dw)));
                }
            }
        }

        // funnel reduction: 7 shfl reduce c[0..7] to root lane sub==k,
        // routing selects run on the (idle) ALU pipe. Same pairwise
        // summation tree per cost as the old 27-shfl butterfly.
        const unsigned FM = 0xffffffffu;
        // xor 4: low half keeps costs 0-3, high half keeps 4-7
        const float d0 = (h4 ? c[4] : c[0]) + __shfl_xor_sync(FM, h4 ? c[0] : c[4], 4);
        const float d1 = (h4 ? c[5] : c[1]) + __shfl_xor_sync(FM, h4 ? c[1] : c[5], 4);
        const float d2 = (h4 ? c[6] : c[2]) + __shfl_xor_sync(FM, h4 ? c[2] : c[6], 4);
        const float d3 = (h4 ? c[7] : c[3]) + __shfl_xor_sync(FM, h4 ? c[3] : c[7], 4);
        // xor 2: keep 2 of 4
        const float e0 = (h2 ? d2 : d0) + __shfl_xor_sync(FM, h2 ? d0 : d2, 2);
        const float e1 = (h2 ? d3 : d1) + __shfl_xor_sync(FM, h2 ? d1 : d3, 2);
        // xor 1: keep 1 of 2 -> lane sub holds full sum of cost sub
        const float fsum = (h1 ? e1 : e0) + __shfl_xor_sync(FM, h1 ? e0 : e1, 1);
        // c[8]: plain 3-round butterfly
        float c8 = c[8];
        c8 += __shfl_xor_sync(FM, c8, 1);
        c8 += __shfl_xor_sync(FM, c8, 2);
        c8 += __shfl_xor_sync(FM, c8, 4);

        g_costs[sub * NPIX + pbase] = fsum;
        if (sub == 0) g_costs[8 * NPIX + pbase] = c8;
    }
}

// ======================= Phase 2: softmax + WLS solve =======================
__device__ __forceinline__ constexpr int tix(int i, int j) { return i * (i + 1) / 2 + j; }

// forward/diag/back substitution with LDL^T factors in m[21], dinv[6]
__device__ __forceinline__ void ldlt_solve(const float* __restrict__ m,
                                           const float* __restrict__ dinv,
                                           float* __restrict__ r)
{
    #pragma unroll
    for (int i = 1; i < 6; i++) {
        #pragma unroll
        for (int k = 0; k < i; k++) r[i] -= m[tix(i, k)] * r[k];
    }
    #pragma unroll
    for (int i = 0; i < 6; i++) r[i] *= dinv[i];
    #pragma unroll
    for (int i = 4; i >= 0; i--) {
        #pragma unroll
        for (int k = i + 1; k < 6; k++) r[i] -= m[tix(k, i)] * r[k];
    }
}

__global__ __launch_bounds__(256, 4)
void solve_kernel(float* __restrict__ out)
{
    const int gid = blockIdx.x * 256 + threadIdx.x;

    float c[9];
    #pragma unroll
    for (int k = 0; k < 9; k++) c[k] = g_costs[k * NPIX + gid];  // coalesced

    float cmin = c[0];
    #pragma unroll
    for (int k = 1; k < 9; k++) cmin = fminf(cmin, c[k]);

    float e[9], S = 0.0f;
    #pragma unroll
    for (int k = 0; k < 9; k++) { e[k] = __expf(cmin - c[k]); S += e[k]; }
    const float inv = 1.0f / S;

    float w[9], q[9];
    #pragma unroll
    for (int k = 0; k < 9; k++) { w[k] = e[k] * inv; q[k] = w[k] * c[k]; }

    // moments of w over {-1,0,1}^2 (x^4=x^2, x^3=x fold)
    const float S20 = w[0] + w[2] + w[3] + w[5] + w[6] + w[8];
    const float S02 = w[0] + w[1] + w[2] + w[6] + w[7] + w[8];
    const float S11 = ((w[0] - w[2]) - w[6]) + w[8];
    const float S10 = ((((-w[0] + w[2]) - w[3]) + w[5]) - w[6]) + w[8];
    const float S01 = ((-w[0] - w[1]) - w[2]) + w[6] + w[7] + w[8];
    const float S21 = ((-w[0] - w[2]) + w[6]) + w[8];
    const float S12 = ((-w[0] + w[2]) - w[6]) + w[8];
    const float S22 = w[0] + w[2] + w[6] + w[8];
    const float S00 = ((((((w[0] + w[1]) + w[2]) + w[3]) + w[4] + w[5]) + w[6]) + w[7]) + w[8];

    const float E = 1e-4f;
    const float a00 = S20 + E, a11 = S02 + E, a22 = S22 + E;
    const float a33 = S20 + E, a44 = S02 + E, a55 = S00 + E;

    float b[6];
    b[0] = q[0] + q[2] + q[3] + q[5] + q[6] + q[8];
    b[1] = q[0] + q[1] + q[2] + q[6] + q[7] + q[8];
    b[2] = ((q[0] - q[2]) - q[6]) + q[8];
    b[3] = ((((-q[0] + q[2]) - q[3]) + q[5]) - q[6]) + q[8];
    b[4] = ((-q[0] - q[1]) - q[2]) + q[6] + q[7] + q[8];
    b[5] = ((((((q[0] + q[1]) + q[2]) + q[3]) + q[4] + q[5]) + q[6]) + q[7]) + q[8];

    // pack symmetric lower triangle, factor LDL^T in place (fp32)
    float m[21];
    m[tix(0,0)] = a00;
    m[tix(1,0)] = S22; m[tix(1,1)] = a11;
    m[tix(2,0)] = S11; m[tix(2,1)] = S11; m[tix(2,2)] = a22;
    m[tix(3,0)] = S10; m[tix(3,1)] = S12; m[tix(3,2)] = S21; m[tix(3,3)] = a33;
    m[tix(4,0)] = S21; m[tix(4,1)] = S01; m[tix(4,2)] = S12; m[tix(4,3)] = S11; m[tix(4,4)] = a44;
    m[tix(5,0)] = S20; m[tix(5,1)] = S02; m[tix(5,2)] = S11; m[tix(5,3)] = S10; m[tix(5,4)] = S01; m[tix(5,5)] = a55;

    // approx reciprocals are fine here: the compensated refinement step below
    // corrects any preconditioner error
    float dinv[6];
    #pragma unroll
    for (int j = 0; j < 6; j++) {
        float d = m[tix(j, j)];
        #pragma unroll
        for (int k = 0; k < j; k++) d -= m[tix(j, k)] * m[tix(j, k)] * m[tix(k, k)];
        m[tix(j, j)] = d;
        const float id = frcp(d);
        dinv[j] = id;
        #pragma unroll
        for (int i = j + 1; i < 6; i++) {
            float s = m[tix(i, j)];
            #pragma unroll
            for (int k = 0; k < j; k++) s -= m[tix(i, k)] * m[tix(j, k)] * m[tix(k, k)];
            m[tix(i, j)] = s * id;
        }
    }

    float x[6];
    #pragma unroll
    for (int i = 0; i < 6; i++) x[i] = b[i];
    ldlt_solve(m, dinv, x);

    // one step of iterative refinement: residual via exact TwoProd/TwoSum
    // (all-fp32 compensated arithmetic; no fp64 anywhere)
    const float Arow[6][6] = {
        { a00, S22, S11, S10, S21, S20 },
        { S22, a11, S11, S12, S01, S02 },
        { S11, S11, a22, S21, S12, S11 },
        { S10, S12, S21, a33, S11, S10 },
        { S21, S01, S12, S11, a44, S01 },
        { S20, S02, S11, S10, S01, a55 }
    };
    float r[6];
    #pragma unroll
    for (int i = 0; i < 6; i++) {
        float s = b[i], t = 0.0f;
        #pragma unroll
        for (int j = 0; j < 6; j++) {
            const float aij = Arow[i][j];
            const float p  = aij * x[j];
            const float ep = fmaf(aij, x[j], -p);   // exact product error
            const float a2 = -p;                    // TwoSum(s, -p)
            const float s2 = s + a2;
            const float v  = s2 - s;
            const float es = (s - (s2 - v)) + (a2 - v);
            s = s2;
            t += es - ep;
        }
        r[i] = s + t;
    }
    ldlt_solve(m, dinv, r);
    #pragma unroll
    for (int i = 0; i < 6; i++) x[i] += r[i];

    float* op = &out[gid * 6];
    #pragma unroll
    for (int i = 0; i < 6; i++) op[i] = x[i];
}

extern "C" void kernel_launch(void* const* d_in, const int* in_sizes, int n_in,
                              void* d_out, int out_size) {
    (void)in_sizes; (void)n_in; (void)out_size;
    const float* feat0 = (const float*)d_in[0];
    const float* feat1 = (const float*)d_in[1];
    const float* flow  = (const float*)d_in[2];
    float* out = (float*)d_out;
    dim3 grid1(XD / 32, YD / 8);
    cost_kernel<<<grid1, 256>>>(feat0, feat1, flow);
    solve_kernel<<<NPIX / 256, 256>>>(out);
}

// round 17
// speedup vs baseline: 1.2377x; 1.0422x over previous
#include <cuda_runtime.h>

#define XD 512
#define YD 384
#define LD 32
#define NPIX (XD * YD)

typedef unsigned long long ull;

__device__ __forceinline__ float4 ld4(const float* p) { return *(const float4*)p; }

// ---- packed f32x2 helpers (sm_100+ PTX only; ptxas never emits these itself) ----
__device__ __forceinline__ ull f2pack(float lo, float hi) {
    ull r; asm("mov.b64 %0,{%1,%2};" : "=l"(r) : "f"(lo), "f"(hi)); return r;
}
__device__ __forceinline__ float2 f2unpack(ull v) {
    float lo, hi; asm("mov.b64 {%0,%1},%2;" : "=f"(lo), "=f"(hi) : "l"(v));
    return make_float2(lo, hi);
}
__device__ __forceinline__ ull f2mul(ull a, ull b) {
    ull r; asm("mul.rn.f32x2 %0,%1,%2;" : "=l"(r) : "l"(a), "l"(b)); return r;
}
__device__ __forceinline__ ull f2add(ull a, ull b) {
    ull r; asm("add.rn.f32x2 %0,%1,%2;" : "=l"(r) : "l"(a), "l"(b)); return r;
}
__device__ __forceinline__ ull f2fma(ull a, ull b, ull c) {
    ull r; asm("fma.rn.f32x2 %0,%1,%2,%3;" : "=l"(r) : "l"(a), "l"(b), "l"(c)); return r;
}
__device__ __forceinline__ float frcp(float x) {
    float r; asm("rcp.approx.ftz.f32 %0,%1;" : "=f"(r) : "f"(x)); return r;
}

__device__ __forceinline__ constexpr int tix(int i, int j) { return i * (i + 1) / 2 + j; }

// forward/diag/back substitution with LDL^T factors in m[21], dinv[6]
__device__ __forceinline__ void ldlt_solve(const float* __restrict__ m,
                                           const float* __restrict__ dinv,
                                           float* __restrict__ r)
{
    #pragma unroll
    for (int i = 1; i < 6; i++) {
        #pragma unroll
        for (int k = 0; k < i; k++) r[i] -= m[tix(i, k)] * r[k];
    }
    #pragma unroll
    for (int i = 0; i < 6; i++) r[i] *= dinv[i];
    #pragma unroll
    for (int i = 4; i >= 0; i--) {
        #pragma unroll
        for (int k = i + 1; k < 6; k++) r[i] -= m[tix(k, i)] * r[k];
    }
}

// ================= Fused: costs (warp-coop) -> smem -> per-thread solve ======
__global__ __launch_bounds__(256, 3)
void quadfit_kernel(const float* __restrict__ feat0,
                    const float* __restrict__ feat1,
                    const float* __restrict__ flow,
                    float* __restrict__ out)
{
    __shared__ float sc[256][9];

    const int tid  = threadIdx.x;
    const int wid  = tid >> 5;
    const int lane = tid & 31;
    const int g    = lane >> 3;   // pixel group within warp (0..3)
    const int sub  = lane & 7;    // channel chunk within pixel (0..7), 4 ch each
    const int bx   = blockIdx.x << 5;
    const int by   = blockIdx.y << 3;
    const int y    = by + wid;
    const bool h4  = (sub & 4) != 0;
    const bool h2  = (sub & 2) != 0;
    const bool h1  = (sub & 1) != 0;

    // prefetch all 8 flow (u,v) pairs up front: 16 independent loads
    float uu[8], vv[8];
    #pragma unroll
    for (int it = 0; it < 8; ++it) {
        const int pb = y * XD + bx + (it << 2) + g;
        uu[it] = flow[pb * 3 + 0];
        vv[it] = flow[pb * 3 + 1];
    }

    #pragma unroll 2
    for (int it = 0; it < 8; ++it) {
        const int lx    = (it << 2) + g;
        const int x     = bx + lx;
        const int pbase = y * XD + x;
        const int pid   = (wid << 5) + lx;

        const float px = (float)x + uu[it];
        const float py = (float)y + vv[it];

        // per-offset frac/floor, computed exactly like the reference
        float fx0, fx1, fx2, fy0, fy1, fy2;
        int ixm, ix0, ixp, iym, iy0, iyp;
        {
            float s, f;
            s = px - 1.0f; f = floorf(s); ixm = (int)f; fx0 = s - f;
            s = px;        f = floorf(s); ix0 = (int)f; fx1 = s - f;
            s = px + 1.0f; f = floorf(s); ixp = (int)f; fx2 = s - f;
            s = py - 1.0f; f = floorf(s); iym = (int)f; fy0 = s - f;
            s = py;        f = floorf(s); iy0 = (int)f; fy1 = s - f;
            s = py + 1.0f; f = floorf(s); iyp = (int)f; fy2 = s - f;
        }

        const float4 f0 = ld4(&feat0[pbase * LD + (sub << 2)]);
        float c[9];

        // fast path: floors consistent AND the full 4x4 tap window interior
        const bool fast = (ixm == ix0 - 1) && (ixp == ix0 + 1)
                       && (iym == iy0 - 1) && (iyp == iy0 + 1)
                       && (ix0 >= 1) && (ix0 <= XD - 3)
                       && (iy0 >= 1) && (iy0 <= YD - 3);
        if (fast) {
            // NOTE: with consistent floors, fx0==fx1==fx2 and fy0==fy1==fy2
            // EXACTLY (Sterbenz), so one packed weight pair serves all lerps.
            const ull WX = f2pack(fx1, fx1), MX = f2pack(1.0f - fx1, 1.0f - fx1);
            const ull WY = f2pack(fy1, fy1), MY = f2pack(1.0f - fy1, 1.0f - fy1);
            const ull NF0 = f2pack(-f0.x, -f0.y);
            const ull NF1 = f2pack(-f0.z, -f0.w);

            ull p0a, p0b, p1a, p1b, p2a, p2b;
            #pragma unroll
            for (int j = 0; j < 4; j++) {
                const float* rp = &feat1[((iy0 - 1 + j) * XD + (ix0 - 1)) * LD + (sub << 2)];
                const ulonglong2 t0 = *(const ulonglong2*)(rp);
                const ulonglong2 t1 = *(const ulonglong2*)(rp + LD);
                const ulonglong2 t2 = *(const ulonglong2*)(rp + 2 * LD);
                const ulonglong2 t3 = *(const ulonglong2*)(rp + 3 * LD);
                // horizontal lerps: h = (1-fx)*left + fx*right
                const ull h0a = f2fma(WX, t1.x, f2mul(MX, t0.x));
                const ull h0b = f2fma(WX, t1.y, f2mul(MX, t0.y));
                const ull h1a = f2fma(WX, t2.x, f2mul(MX, t1.x));
                const ull h1b = f2fma(WX, t2.y, f2mul(MX, t1.y));
                const ull h2a = f2fma(WX, t3.x, f2mul(MX, t2.x));
                const ull h2b = f2fma(WX, t3.y, f2mul(MX, t2.y));
                if (j > 0) {
                    {   // sample column 0
                        const ull sa = f2fma(WY, h0a, f2mul(MY, p0a));
                        const ull sb = f2fma(WY, h0b, f2mul(MY, p0b));
                        const ull da = f2add(sa, NF0), db = f2add(sb, NF1);
                        const float2 cu = f2unpack(f2fma(db, db, f2mul(da, da)));
                        c[(j - 1) * 3 + 0] = cu.x + cu.y;
                    }
                    {   // sample column 1
                        const ull sa = f2fma(WY, h1a, f2mul(MY, p1a));
                        const ull sb = f2fma(WY, h1b, f2mul(MY, p1b));
                        const ull da = f2add(sa, NF0), db = f2add(sb, NF1);
                        const float2 cu = f2unpack(f2fma(db, db, f2mul(da, da)));
                        c[(j - 1) * 3 + 1] = cu.x + cu.y;
                    }
                    {   // sample column 2
                        const ull sa = f2fma(WY, h2a, f2mul(MY, p2a));
                        const ull sb = f2fma(WY, h2b, f2mul(MY, p2b));
                        const ull da = f2add(sa, NF0), db = f2add(sb, NF1);
                        const float2 cu = f2unpack(f2fma(db, db, f2mul(da, da)));
                        c[(j - 1) * 3 + 2] = cu.x + cu.y;
                    }
                }
                p0a = h0a; p0b = h0b; p1a = h1a; p1b = h1b; p2a = h2a; p2b = h2b;
            }
        } else {
            // exact reference clamp protocol (border pixels):
            //   t0 = clamp(floor(p), 0, D-1);  t1 = min(t0 + 1, D-1)
            const int   ixs[3] = {ixm, ix0, ixp};
            const int   iys[3] = {iym, iy0, iyp};
            const float fxs[3] = {fx0, fx1, fx2};
            const float fys[3] = {fy0, fy1, fy2};
            int xs0[3], xs1[3], ys0[3], ys1[3];
            #pragma unroll
            for (int o = 0; o < 3; o++) {
                xs0[o] = min(max(ixs[o], 0), XD - 1);
                xs1[o] = min(xs0[o] + 1, XD - 1);
                ys0[o] = min(max(iys[o], 0), YD - 1);
                ys1[o] = min(ys0[o] + 1, YD - 1);
            }
            #pragma unroll
            for (int p = 0; p < 3; p++) {
                #pragma unroll
                for (int o = 0; o < 3; o++) {
                    const float wx = fxs[o], wy = fys[p];
                    const float4 f00 = ld4(&feat1[(ys0[p] * XD + xs0[o]) * LD + (sub << 2)]);
                    const float4 f01 = ld4(&feat1[(ys0[p] * XD + xs1[o]) * LD + (sub << 2)]);
                    const float4 f10 = ld4(&feat1[(ys1[p] * XD + xs0[o]) * LD + (sub << 2)]);
                    const float4 f11 = ld4(&feat1[(ys1[p] * XD + xs1[o]) * LD + (sub << 2)]);
                    const float w00 = (1.0f - wx) * (1.0f - wy);
                    const float w01 = wx * (1.0f - wy);
                    const float w10 = (1.0f - wx) * wy;
                    const float w11 = wx * wy;
                    float4 s4;
                    s4.x = fmaf(f00.x, w00, fmaf(f01.x, w01, fmaf(f10.x, w10, f11.x * w11)));
                    s4.y = fmaf(f00.y, w00, fmaf(f01.y, w01, fmaf(f10.y, w10, f11.y * w11)));
                    s4.z = fmaf(f00.z, w00, fmaf(f01.z, w01, fmaf(f10.z, w10, f11.z * w11)));
                    s4.w = fmaf(f00.w, w00, fmaf(f01.w, w01, fmaf(f10.w, w10, f11.w * w11)));
                    const float dx = s4.x - f0.x, dy = s4.y - f0.y;
                    const float dz = s4.z - f0.z, dw = s4.w - f0.w;
                    c[p * 3 + o] = fmaf(dx, dx, fmaf(dy, dy, fmaf(dz, dz, dw * dw)));
                }
            }
        }

        // funnel reduction: 7 shfl reduce c[0..7] to root lane sub==k.
        // Same pairwise summation tree per cost as a full xor butterfly.
        const unsigned FM = 0xffffffffu;
        const float d0 = (h4 ? c[4] : c[0]) + __shfl_xor_sync(FM, h4 ? c[0] : c[4], 4);
        const float d1 = (h4 ? c[5] : c[1]) + __shfl_xor_sync(FM, h4 ? c[1] : c[5], 4);
        const float d2 = (h4 ? c[6] : c[2]) + __shfl_xor_sync(FM, h4 ? c[2] : c[6], 4);
        const float d3 = (h4 ? c[7] : c[3]) + __shfl_xor_sync(FM, h4 ? c[3] : c[7], 4);
        const float e0 = (h2 ? d2 : d0) + __shfl_xor_sync(FM, h2 ? d0 : d2, 2);
        const float e1 = (h2 ? d3 : d1) + __shfl_xor_sync(FM, h2 ? d1 : d3, 2);
        const float fsum = (h1 ? e1 : e0) + __shfl_xor_sync(FM, h1 ? e0 : e1, 1);
        float c8 = c[8];
        c8 += __shfl_xor_sync(FM, c8, 1);
        c8 += __shfl_xor_sync(FM, c8, 2);
        c8 += __shfl_xor_sync(FM, c8, 4);

        sc[pid][sub] = fsum;
        if (sub == 0) sc[pid][8] = c8;
    }

    __syncthreads();

    // ---------------- Phase 2: one pixel per thread (softmax + WLS) ---------
    {
        float c[9];
        #pragma unroll
        for (int k = 0; k < 9; k++) c[k] = sc[tid][k];

        float cmin = c[0];
        #pragma unroll
        for (int k = 1; k < 9; k++) cmin = fminf(cmin, c[k]);

        float e[9], S = 0.0f;
        #pragma unroll
        for (int k = 0; k < 9; k++) { e[k] = __expf(cmin - c[k]); S += e[k]; }
        const float inv = 1.0f / S;

        float w[9], q[9];
        #pragma unroll
        for (int k = 0; k < 9; k++) { w[k] = e[k] * inv; q[k] = w[k] * c[k]; }

        // moments of w over {-1,0,1}^2 (x^4=x^2, x^3=x fold)
        const float S20 = w[0] + w[2] + w[3] + w[5] + w[6] + w[8];
        const float S02 = w[0] + w[1] + w[2] + w[6] + w[7] + w[8];
        const float S11 = ((w[0] - w[2]) - w[6]) + w[8];
        const float S10 = ((((-w[0] + w[2]) - w[3]) + w[5]) - w[6]) + w[8];
        const float S01 = ((-w[0] - w[1]) - w[2]) + w[6] + w[7] + w[8];
        const float S21 = ((-w[0] - w[2]) + w[6]) + w[8];
        const float S12 = ((-w[0] + w[2]) - w[6]) + w[8];
        const float S22 = w[0] + w[2] + w[6] + w[8];
        const float S00 = ((((((w[0] + w[1]) + w[2]) + w[3]) + w[4] + w[5]) + w[6]) + w[7]) + w[8];

        const float E = 1e-4f;
        const float a00 = S20 + E, a11 = S02 + E, a22 = S22 + E;
        const float a33 = S20 + E, a44 = S02 + E, a55 = S00 + E;

        float b[6];
        b[0] = q[0] + q[2] + q[3] + q[5] + q[6] + q[8];
        b[1] = q[0] + q[1] + q[2] + q[6] + q[7] + q[8];
        b[2] = ((q[0] - q[2]) - q[6]) + q[8];
        b[3] = ((((-q[0] + q[2]) - q[3]) + q[5]) - q[6]) + q[8];
        b[4] = ((-q[0] - q[1]) - q[2]) + q[6] + q[7] + q[8];
        b[5] = ((((((q[0] + q[1]) + q[2]) + q[3]) + q[4] + q[5]) + q[6]) + q[7]) + q[8];

        // pack symmetric lower triangle, factor LDL^T in place (fp32)
        float m[21];
        m[tix(0,0)] = a00;
        m[tix(1,0)] = S22; m[tix(1,1)] = a11;
        m[tix(2,0)] = S11; m[tix(2,1)] = S11; m[tix(2,2)] = a22;
        m[tix(3,0)] = S10; m[tix(3,1)] = S12; m[tix(3,2)] = S21; m[tix(3,3)] = a33;
        m[tix(4,0)] = S21; m[tix(4,1)] = S01; m[tix(4,2)] = S12; m[tix(4,3)] = S11; m[tix(4,4)] = a44;
        m[tix(5,0)] = S20; m[tix(5,1)] = S02; m[tix(5,2)] = S11; m[tix(5,3)] = S10; m[tix(5,4)] = S01; m[tix(5,5)] = a55;

        // approx reciprocals fine: refinement below corrects preconditioner error
        float dinv[6];
        #pragma unroll
        for (int j = 0; j < 6; j++) {
            float d = m[tix(j, j)];
            #pragma unroll
            for (int k = 0; k < j; k++) d -= m[tix(j, k)] * m[tix(j, k)] * m[tix(k, k)];
            m[tix(j, j)] = d;
            const float id = frcp(d);
            dinv[j] = id;
            #pragma unroll
            for (int i = j + 1; i < 6; i++) {
                float s = m[tix(i, j)];
                #pragma unroll
                for (int k = 0; k < j; k++) s -= m[tix(i, k)] * m[tix(j, k)] * m[tix(k, k)];
                m[tix(i, j)] = s * id;
            }
        }

        float x[6];
        #pragma unroll
        for (int i = 0; i < 6; i++) x[i] = b[i];
        ldlt_solve(m, dinv, x);

        // one step of iterative refinement: residual via exact TwoProd/TwoSum
        const float Arow[6][6] = {
            { a00, S22, S11, S10, S21, S20 },
            { S22, a11, S11, S12, S01, S02 },
            { S11, S11, a22, S21, S12, S11 },
            { S10, S12, S21, a33, S11, S10 },
            { S21, S01, S12, S11, a44, S01 },
            { S20, S02, S11, S10, S01, a55 }
        };
        float r[6];
        #pragma unroll
        for (int i = 0; i < 6; i++) {
            float s = b[i], t = 0.0f;
            #pragma unroll
            for (int j = 0; j < 6; j++) {
                const float aij = Arow[i][j];
                const float p  = aij * x[j];
                const float ep = fmaf(aij, x[j], -p);   // exact product error
                const float a2 = -p;                    // TwoSum(s, -p)
                const float s2 = s + a2;
                const float v  = s2 - s;
                const float es = (s - (s2 - v)) + (a2 - v);
                s = s2;
                t += es - ep;
            }
            r[i] = s + t;
        }
        ldlt_solve(m, dinv, r);
        #pragma unroll
        for (int i = 0; i < 6; i++) x[i] += r[i];

        const int gx = bx + (tid & 31);
        const int gy = by + (tid >> 5);
        float* op = &out[(gy * XD + gx) * 6];
        #pragma unroll
        for (int i = 0; i < 6; i++) op[i] = x[i];
    }
}

extern "C" void kernel_launch(void* const* d_in, const int* in_sizes, int n_in,
                              void* d_out, int out_size) {
    (void)in_sizes; (void)n_in; (void)out_size;
    const float* feat0 = (const float*)d_in[0];
    const float* feat1 = (const float*)d_in[1];
    const float* flow  = (const float*)d_in[2];
    float* out = (float*)d_out;
    dim3 grid(XD / 32, YD / 8);
    quadfit_kernel<<<grid, 256>>>(feat0, feat1, flow, out);
}